// round 1
// baseline (speedup 1.0000x reference)
#include <cuda_runtime.h>

#define BATCH 2
#define TSEQ 2048
#define CEMB 2048
#define NHEAD 16
#define LDIM 128
#define MROWS (BATCH*TSEQ)

// Scratch (allocation-free rule: __device__ globals)
__device__ float g_k[BATCH*TSEQ*LDIM];          //  2 MB  [b*T + s][L]
__device__ float g_q[BATCH*NHEAD*TSEQ*LDIM];    // 32 MB  [(b*NH+h)*T + t][L]
__device__ float g_y[BATCH*TSEQ*NHEAD*LDIM];    // 32 MB  [b*T + t][h*L + l]

// ---------------------------------------------------------------------------
// SGEMM: C[M,N] = A[M,K] @ B[K,N] + bias[N]
// 128x128 block tile, BK=16, 256 threads, 8x8 per-thread fragment (split 4+4).
// MODE 0: row-major output. MODE 1: q-layout output [(b*NH+h)*T + t][L].
// ---------------------------------------------------------------------------
template<int MODE>
__global__ void sgemm_kernel(const float* __restrict__ A,
                             const float* __restrict__ Bm,
                             const float* __restrict__ bias,
                             float* __restrict__ Cout,
                             int Mdim, int Ndim, int Kdim)
{
    __shared__ float As[16][132];   // [k][m] (transposed)
    __shared__ float Bs[16][132];   // [k][n]

    const int tid = threadIdx.x;
    const int tx = tid & 15, ty = tid >> 4;
    const int m0 = blockIdx.y << 7, n0 = blockIdx.x << 7;

    float acc[2][2][4][4];
    #pragma unroll
    for (int a = 0; a < 2; a++)
        #pragma unroll
        for (int c = 0; c < 2; c++)
            #pragma unroll
            for (int i = 0; i < 4; i++)
                #pragma unroll
                for (int j = 0; j < 4; j++) acc[a][c][i][j] = 0.f;

    const int arow = tid >> 1, ak = (tid & 1) * 8;   // A tile: 128 rows x 16 k
    const int brow = tid >> 4, bc = (tid & 15) * 8;  // B tile: 16 k x 128 cols
    const float* Ap = A + (size_t)(m0 + arow) * Kdim + ak;
    const float* Bp = Bm + (size_t)brow * Ndim + n0 + bc;

    for (int k0 = 0; k0 < Kdim; k0 += 16) {
        float4 a0 = *(const float4*)(Ap + k0);
        float4 a1 = *(const float4*)(Ap + k0 + 4);
        float4 b0 = *(const float4*)(Bp + (size_t)k0 * Ndim);
        float4 b1 = *(const float4*)(Bp + (size_t)k0 * Ndim + 4);
        __syncthreads();
        As[ak+0][arow] = a0.x; As[ak+1][arow] = a0.y;
        As[ak+2][arow] = a0.z; As[ak+3][arow] = a0.w;
        As[ak+4][arow] = a1.x; As[ak+5][arow] = a1.y;
        As[ak+6][arow] = a1.z; As[ak+7][arow] = a1.w;
        *(float4*)&Bs[brow][bc]     = b0;
        *(float4*)&Bs[brow][bc + 4] = b1;
        __syncthreads();

        #pragma unroll
        for (int k = 0; k < 16; k++) {
            float4 av0 = *(const float4*)&As[k][4*ty];
            float4 av1 = *(const float4*)&As[k][64 + 4*ty];
            float4 bv0 = *(const float4*)&Bs[k][4*tx];
            float4 bv1 = *(const float4*)&Bs[k][64 + 4*tx];
            float ar[8] = {av0.x,av0.y,av0.z,av0.w, av1.x,av1.y,av1.z,av1.w};
            float br[8] = {bv0.x,bv0.y,bv0.z,bv0.w, bv1.x,bv1.y,bv1.z,bv1.w};
            #pragma unroll
            for (int i = 0; i < 8; i++)
                #pragma unroll
                for (int j = 0; j < 8; j++)
                    acc[i>>2][j>>2][i&3][j&3] += ar[i] * br[j];
        }
    }

    #pragma unroll
    for (int im = 0; im < 2; im++)
        #pragma unroll
        for (int i = 0; i < 4; i++) {
            const int m = m0 + im*64 + 4*ty + i;
            #pragma unroll
            for (int in = 0; in < 2; in++) {
                const int nb = n0 + in*64 + 4*tx;
                float4 v;
                v.x = acc[im][in][i][0] + bias[nb+0];
                v.y = acc[im][in][i][1] + bias[nb+1];
                v.z = acc[im][in][i][2] + bias[nb+2];
                v.w = acc[im][in][i][3] + bias[nb+3];
                if (MODE == 0) {
                    *(float4*)&Cout[(size_t)m * Ndim + nb] = v;
                } else {
                    // q layout: (b,t) = m, (h,l) = n  ->  [(b*NH+h)*T + t][l]
                    const int b = m / TSEQ, t = m % TSEQ;
                    const int h = nb / LDIM, l = nb % LDIM;
                    *(float4*)&Cout[(((size_t)(b*NHEAD + h))*TSEQ + t)*LDIM + l] = v;
                }
            }
        }
}

// ---------------------------------------------------------------------------
// Flash attention with shared latent (K == V).
// Grid: (T/64 q-tiles, B*NH). 256 threads. 64-row Q tile per CTA.
// Online softmax stats replicated in registers via width-16 shuffles.
// ---------------------------------------------------------------------------
__global__ void attn_kernel(const float* __restrict__ gq,
                            const float* __restrict__ gk,
                            float* __restrict__ gy)
{
    extern __shared__ float sm[];
    float* Qs = sm;                  // 64 x 132
    float* Ks = sm + 64*132;         // 64 x 132
    float* Ps = sm + 2*64*132;       // 64 x 68

    const int tid = threadIdx.x;
    const int tx = tid & 15, ty = tid >> 4;
    const int qt = blockIdx.x;
    const int bh = blockIdx.y;
    const int b = bh >> 4, h = bh & 15;

    const float* qbase = gq + ((size_t)bh * TSEQ + qt*64) * LDIM;
    const float* kbase = gk + (size_t)b * TSEQ * LDIM;

    // Load Q tile (64 x 128)
    #pragma unroll
    for (int u = 0; u < 8; u++) {
        int lin = u*256 + tid;
        int row = lin >> 5, c4 = (lin & 31) << 2;
        *(float4*)&Qs[row*132 + c4] = *(const float4*)(qbase + row*LDIM + c4);
    }

    float yacc[4][8];
    #pragma unroll
    for (int i = 0; i < 4; i++)
        #pragma unroll
        for (int j = 0; j < 8; j++) yacc[i][j] = 0.f;
    float m_r[4] = {-1e30f,-1e30f,-1e30f,-1e30f};
    float l_r[4] = {0.f,0.f,0.f,0.f};
    const float scale = 0.08838834764831845f;   // 1/sqrt(128)

    for (int kt = 0; kt <= qt; kt++) {
        __syncthreads();   // previous iteration's Y-phase done with Ks
        #pragma unroll
        for (int u = 0; u < 8; u++) {
            int lin = u*256 + tid;
            int row = lin >> 5, c4 = (lin & 31) << 2;
            *(float4*)&Ks[row*132 + c4] =
                *(const float4*)(kbase + (size_t)(kt*64 + row)*LDIM + c4);
        }
        __syncthreads();

        // S = Q K^T : rows 4ty+i, cols tx+16j (strided for conflict-free LDS)
        float sacc[4][4];
        #pragma unroll
        for (int i = 0; i < 4; i++)
            #pragma unroll
            for (int j = 0; j < 4; j++) sacc[i][j] = 0.f;

        #pragma unroll 2
        for (int kk = 0; kk < 128; kk += 4) {
            float4 qv[4], kv[4];
            #pragma unroll
            for (int i = 0; i < 4; i++)
                qv[i] = *(const float4*)&Qs[(4*ty+i)*132 + kk];
            #pragma unroll
            for (int j = 0; j < 4; j++)
                kv[j] = *(const float4*)&Ks[(tx + 16*j)*132 + kk];
            #pragma unroll
            for (int i = 0; i < 4; i++)
                #pragma unroll
                for (int j = 0; j < 4; j++)
                    sacc[i][j] += qv[i].x*kv[j].x + qv[i].y*kv[j].y
                                + qv[i].z*kv[j].z + qv[i].w*kv[j].w;
        }

        // scale + causal mask (only the diagonal tile needs masking)
        if (kt == qt) {
            #pragma unroll
            for (int i = 0; i < 4; i++)
                #pragma unroll
                for (int j = 0; j < 4; j++) {
                    if (tx + 16*j > 4*ty + i) sacc[i][j] = -1e30f;
                    else                      sacc[i][j] *= scale;
                }
        } else {
            #pragma unroll
            for (int i = 0; i < 4; i++)
                #pragma unroll
                for (int j = 0; j < 4; j++) sacc[i][j] *= scale;
        }

        // Online softmax: width-16 shuffle reductions; stats replicated per lane
        #pragma unroll
        for (int i = 0; i < 4; i++) {
            float rmax = fmaxf(fmaxf(sacc[i][0], sacc[i][1]),
                               fmaxf(sacc[i][2], sacc[i][3]));
            #pragma unroll
            for (int off = 8; off > 0; off >>= 1)
                rmax = fmaxf(rmax, __shfl_xor_sync(0xffffffffu, rmax, off, 16));
            float mnew = fmaxf(m_r[i], rmax);
            float p0 = __expf(sacc[i][0] - mnew);
            float p1 = __expf(sacc[i][1] - mnew);
            float p2 = __expf(sacc[i][2] - mnew);
            float p3 = __expf(sacc[i][3] - mnew);
            float rsum = p0 + p1 + p2 + p3;
            #pragma unroll
            for (int off = 8; off > 0; off >>= 1)
                rsum += __shfl_xor_sync(0xffffffffu, rsum, off, 16);
            float corr = __expf(m_r[i] - mnew);
            l_r[i] = l_r[i]*corr + rsum;
            m_r[i] = mnew;
            Ps[(4*ty+i)*68 + tx]      = p0;
            Ps[(4*ty+i)*68 + tx + 16] = p1;
            Ps[(4*ty+i)*68 + tx + 32] = p2;
            Ps[(4*ty+i)*68 + tx + 48] = p3;
            #pragma unroll
            for (int j = 0; j < 8; j++) yacc[i][j] *= corr;
        }
        __syncwarp();   // Ps rows are warp-private: warp sync suffices

        // Y += P @ K  (K doubles as V): cols 4tx..+3 and 64+4tx..+3
        #pragma unroll 2
        for (int s0 = 0; s0 < 64; s0 += 4) {
            float4 pv[4];
            #pragma unroll
            for (int i = 0; i < 4; i++)
                pv[i] = *(const float4*)&Ps[(4*ty+i)*68 + s0];
            #pragma unroll
            for (int u = 0; u < 4; u++) {
                float4 k0v = *(const float4*)&Ks[(s0+u)*132 + 4*tx];
                float4 k1v = *(const float4*)&Ks[(s0+u)*132 + 64 + 4*tx];
                #pragma unroll
                for (int i = 0; i < 4; i++) {
                    float p = (u==0) ? pv[i].x : (u==1) ? pv[i].y
                            : (u==2) ? pv[i].z : pv[i].w;
                    yacc[i][0] += p*k0v.x; yacc[i][1] += p*k0v.y;
                    yacc[i][2] += p*k0v.z; yacc[i][3] += p*k0v.w;
                    yacc[i][4] += p*k1v.x; yacc[i][5] += p*k1v.y;
                    yacc[i][6] += p*k1v.z; yacc[i][7] += p*k1v.w;
                }
            }
        }
    }

    // Epilogue: normalize and write y in [b*T + t][h*L + l] layout
    #pragma unroll
    for (int i = 0; i < 4; i++) {
        float linv = 1.0f / l_r[i];
        int grow = qt*64 + 4*ty + i;
        size_t orow = ((size_t)b*TSEQ + grow)*(NHEAD*LDIM) + (size_t)h*LDIM;
        float4 v0 = make_float4(yacc[i][0]*linv, yacc[i][1]*linv,
                                yacc[i][2]*linv, yacc[i][3]*linv);
        float4 v1 = make_float4(yacc[i][4]*linv, yacc[i][5]*linv,
                                yacc[i][6]*linv, yacc[i][7]*linv);
        *(float4*)&gy[orow + 4*tx]      = v0;
        *(float4*)&gy[orow + 64 + 4*tx] = v1;
    }
}

// ---------------------------------------------------------------------------
extern "C" void kernel_launch(void* const* d_in, const int* in_sizes, int n_in,
                              void* d_out, int out_size)
{
    const float* x      = (const float*)d_in[0];
    const float* W_lat  = (const float*)d_in[1];
    const float* b_lat  = (const float*)d_in[2];
    const float* W_d    = (const float*)d_in[3];
    const float* b_d    = (const float*)d_in[4];
    const float* W_proj = (const float*)d_in[5];
    const float* b_proj = (const float*)d_in[6];
    float* out = (float*)d_out;

    float *kp, *qp, *yp;
    cudaGetSymbolAddress((void**)&kp, g_k);
    cudaGetSymbolAddress((void**)&qp, g_q);
    cudaGetSymbolAddress((void**)&yp, g_y);

    dim3 blk(256);

    // 1) k = x @ W_lat + b_lat            [4096,128]
    sgemm_kernel<0><<<dim3(1, MROWS/128), blk>>>(x, W_lat, b_lat, kp,
                                                 MROWS, LDIM, CEMB);
    // 2) q = x @ W_d + b_d  -> [B,H,T,L]  [4096,2048]
    sgemm_kernel<1><<<dim3((NHEAD*LDIM)/128, MROWS/128), blk>>>(x, W_d, b_d, qp,
                                                 MROWS, NHEAD*LDIM, CEMB);
    // 3) flash attention (K == V)
    const int attn_smem = (2*64*132 + 64*68) * (int)sizeof(float);  // 84,992 B
    cudaFuncSetAttribute(attn_kernel,
                         cudaFuncAttributeMaxDynamicSharedMemorySize, attn_smem);
    attn_kernel<<<dim3(TSEQ/64, BATCH*NHEAD), blk, attn_smem>>>(qp, kp, yp);

    // 4) out = y @ W_proj + b_proj        [4096,2048]
    sgemm_kernel<0><<<dim3(CEMB/128, MROWS/128), blk>>>(yp, W_proj, b_proj, out,
                                                 MROWS, CEMB, CEMB);
}

// round 5
// speedup vs baseline: 1.0342x; 1.0342x over previous
#include <cuda_runtime.h>
#include <cuda_bf16.h>
#include <cstdint>

#define BATCH 2
#define TSEQ 2048
#define CEMB 2048
#define NHEAD 16
#define LDIM 128
#define MROWS (BATCH*TSEQ)
#define QSTR (NHEAD*LDIM)   // 2048

// ---------------------------------------------------------------------------
// Scratch (__device__ globals: allocation-free rule)
// ---------------------------------------------------------------------------
__device__ float g_k[BATCH*TSEQ*LDIM];               //  2 MB fp32 latent
__device__ float g_q[MROWS*QSTR];                    // 32 MB fp32 q
__device__ float g_y[MROWS*QSTR];                    // 32 MB fp32 y
__device__ __nv_bfloat16 g_xh[MROWS*CEMB];           // x hi
__device__ __nv_bfloat16 g_xl[MROWS*CEMB];           // x lo
__device__ __nv_bfloat16 g_yh[MROWS*QSTR];           // y hi
__device__ __nv_bfloat16 g_yl[MROWS*QSTR];           // y lo
__device__ uint32_t g_wdh[(CEMB/2)*QSTR];            // W_d hi, k-pair packed
__device__ uint32_t g_wdl[(CEMB/2)*QSTR];
__device__ uint32_t g_wph[(QSTR/2)*CEMB];            // W_proj
__device__ uint32_t g_wpl[(QSTR/2)*CEMB];
__device__ uint32_t g_wlh[(CEMB/2)*LDIM];            // W_lat
__device__ uint32_t g_wll[(CEMB/2)*LDIM];

__device__ __forceinline__ uint32_t smem_u32(const void* p){
    uint32_t a;
    asm("{ .reg .u64 t; cvta.to.shared.u64 t, %1; cvt.u32.u64 %0, t; }"
        : "=r"(a) : "l"(p));
    return a;
}

#define CP16(dst_u32, src_ptr) \
    asm volatile("cp.async.cg.shared.global [%0], [%1], 16;" \
                 :: "r"(dst_u32), "l"(src_ptr) : "memory")

// ---------------------------------------------------------------------------
// Split fp32 -> (hi, lo) bf16, elementwise (for A-side operands)
// ---------------------------------------------------------------------------
__global__ void split_rows(const float* __restrict__ src,
                           __nv_bfloat16* __restrict__ hi,
                           __nv_bfloat16* __restrict__ lo, int n)
{
    int i = (blockIdx.x * 256 + threadIdx.x) * 4;
    if (i >= n) return;
    float4 v = *(const float4*)(src + i);
    __nv_bfloat16 h0 = __float2bfloat16(v.x), h1 = __float2bfloat16(v.y);
    __nv_bfloat16 h2 = __float2bfloat16(v.z), h3 = __float2bfloat16(v.w);
    __nv_bfloat162* H = (__nv_bfloat162*)(hi + i);
    __nv_bfloat162* L = (__nv_bfloat162*)(lo + i);
    H[0] = __nv_bfloat162(h0, h1); H[1] = __nv_bfloat162(h2, h3);
    L[0] = __nv_bfloat162(__float2bfloat16(v.x - __bfloat162float(h0)),
                          __float2bfloat16(v.y - __bfloat162float(h1)));
    L[1] = __nv_bfloat162(__float2bfloat16(v.z - __bfloat162float(h2)),
                          __float2bfloat16(v.w - __bfloat162float(h3)));
}

// ---------------------------------------------------------------------------
// Split + k-pair-pack fp32 W[K][N] -> hi/lo uint32[(K/2)][N]
// uint32 = (bf16 of W[2kp][n]) | (bf16 of W[2kp+1][n]) << 16
// ---------------------------------------------------------------------------
__global__ void split_pack(const float* __restrict__ W,
                           uint32_t* __restrict__ hp,
                           uint32_t* __restrict__ lp, int K, int N)
{
    int idx = blockIdx.x * 256 + threadIdx.x;
    int total = (K >> 1) * N;
    if (idx >= total) return;
    int kp = idx / N, n = idx - kp * N;
    float v0 = W[(size_t)(2*kp) * N + n];
    float v1 = W[(size_t)(2*kp+1) * N + n];
    __nv_bfloat16 h0 = __float2bfloat16(v0), h1 = __float2bfloat16(v1);
    __nv_bfloat16 l0 = __float2bfloat16(v0 - __bfloat162float(h0));
    __nv_bfloat16 l1 = __float2bfloat16(v1 - __bfloat162float(h1));
    hp[idx] = (uint32_t)__bfloat16_as_ushort(h0)
            | ((uint32_t)__bfloat16_as_ushort(h1) << 16);
    lp[idx] = (uint32_t)__bfloat16_as_ushort(l0)
            | ((uint32_t)__bfloat16_as_ushort(l1) << 16);
}

// ---------------------------------------------------------------------------
// bf16x3 GEMM:  C[M,N] = A[M,K] @ B[K,N] + bias[N]   (fp32-grade accuracy)
// A: hi/lo bf16 row-major. B: hi/lo uint32 k-pair packed [K/2][N].
// CTA 128x128, BK=32, 256 thr (8 warps 4x2), warp 32x64, m16n8k16 mma,
// 3 mma per fragment pair: ahi*bhi + ahi*blo + alo*bhi. cp.async dbl-buffer.
// ---------------------------------------------------------------------------
#define AS_U32 20                     // 8 data + 12 pad... (8 u32 data, stride 20)
#define BS_U32 136                    // 128 data + 8 pad
#define ABYTES (128*AS_U32*4)         // 10240 per hi|lo
#define BBYTES (16*BS_U32*4)          // 8704 per hi|lo
#define OFF_AL (ABYTES)               // 10240
#define OFF_BH (2*ABYTES)             // 20480
#define OFF_BL (2*ABYTES + BBYTES)    // 29184
#define STAGE  (2*ABYTES + 2*BBYTES)  // 37888
#define GEMM_SMEM (2*STAGE)           // 75776

#define MMA_BF16(acc, a, b0, b1)                                              \
    asm volatile(                                                             \
        "mma.sync.aligned.m16n8k16.row.col.f32.bf16.bf16.f32 "                \
        "{%0,%1,%2,%3}, {%4,%5,%6,%7}, {%8,%9}, {%0,%1,%2,%3};"               \
        : "+f"((acc)[0]), "+f"((acc)[1]), "+f"((acc)[2]), "+f"((acc)[3])      \
        : "r"((a)[0]), "r"((a)[1]), "r"((a)[2]), "r"((a)[3]),                 \
          "r"(b0), "r"(b1))

__global__ void __launch_bounds__(256, 2)
gemm_bf16x3(const __nv_bfloat16* __restrict__ Ah,
            const __nv_bfloat16* __restrict__ Al,
            const uint32_t* __restrict__ Bh,
            const uint32_t* __restrict__ Bl,
            const float* __restrict__ bias, float* __restrict__ C,
            int Ndim, int Kdim)
{
    extern __shared__ char sm[];
    const uint32_t smb = smem_u32(sm);

    const int tid = threadIdx.x;
    const int lane = tid & 31, wid = tid >> 5;
    const int warp_row = wid & 3;          // 4 x 32 rows
    const int warp_col = wid >> 2;         // 2 x 64 cols
    const int m0 = blockIdx.y << 7, n0 = blockIdx.x << 7;
    const int lr = lane >> 2, lc = lane & 3;

    float acc[2][8][4];
    #pragma unroll
    for (int mt = 0; mt < 2; mt++)
        #pragma unroll
        for (int nt = 0; nt < 8; nt++)
            #pragma unroll
            for (int i = 0; i < 4; i++) acc[mt][nt][i] = 0.f;

    // copy coords: A: 512 chunks of 16B (128 rows x 4); B: 512 (16 kp x 32)
    const int ar = tid >> 2, ac = tid & 3;      // rows 0..63 (p adds 64)
    const int bk = tid >> 5, bc = tid & 31;     // kp 0..7 (p adds 8)

    const int nk = Kdim >> 5;

    auto issue = [&](int kc) {
        const uint32_t base = smb + (kc & 1) * STAGE;
        const int k0 = kc << 5, kp0 = kc << 4;
        #pragma unroll
        for (int p = 0; p < 2; p++) {
            int row = p * 64 + ar;
            uint32_t d = base + row * (AS_U32*4) + ac * 16;
            const __nv_bfloat16* sa = Ah + (size_t)(m0 + row) * Kdim + k0 + ac * 8;
            const __nv_bfloat16* sl = Al + (size_t)(m0 + row) * Kdim + k0 + ac * 8;
            CP16(d, sa);
            CP16(d + OFF_AL, sl);
        }
        #pragma unroll
        for (int p = 0; p < 2; p++) {
            int kp = p * 8 + bk;
            uint32_t d = base + kp * (BS_U32*4) + bc * 16;
            const uint32_t* sh = Bh + (size_t)(kp0 + kp) * Ndim + n0 + bc * 4;
            const uint32_t* slo = Bl + (size_t)(kp0 + kp) * Ndim + n0 + bc * 4;
            CP16(d + OFF_BH, sh);
            CP16(d + OFF_BL, slo);
        }
        asm volatile("cp.async.commit_group;" ::: "memory");
    };

    issue(0);
    if (nk > 1) issue(1);

    for (int kc = 0; kc < nk; kc++) {
        if (kc + 1 < nk) asm volatile("cp.async.wait_group 1;" ::: "memory");
        else             asm volatile("cp.async.wait_group 0;" ::: "memory");
        __syncthreads();

        const uint32_t* S = (const uint32_t*)(sm + (kc & 1) * STAGE);
        const uint32_t* sAh = S;
        const uint32_t* sAl = S + ABYTES/4;
        const uint32_t* sBh = S + 2*(ABYTES/4);
        const uint32_t* sBl = S + 2*(ABYTES/4) + BBYTES/4;

        #pragma unroll
        for (int ks = 0; ks < 2; ks++) {
            uint32_t ahi[2][4], alo[2][4];
            #pragma unroll
            for (int mt = 0; mt < 2; mt++) {
                int r0 = (warp_row*32 + mt*16 + lr) * AS_U32 + ks*8 + lc;
                int r8 = r0 + 8 * AS_U32;
                ahi[mt][0] = sAh[r0];     ahi[mt][1] = sAh[r8];
                ahi[mt][2] = sAh[r0 + 4]; ahi[mt][3] = sAh[r8 + 4];
                alo[mt][0] = sAl[r0];     alo[mt][1] = sAl[r8];
                alo[mt][2] = sAl[r0 + 4]; alo[mt][3] = sAl[r8 + 4];
            }
            #pragma unroll
            for (int nt = 0; nt < 8; nt++) {
                int c0 = (ks*8 + lc) * BS_U32 + warp_col*64 + nt*8 + lr;
                int c4 = c0 + 4 * BS_U32;
                uint32_t bh0 = sBh[c0], bh1 = sBh[c4];
                uint32_t bl0 = sBl[c0], bl1 = sBl[c4];
                #pragma unroll
                for (int mt = 0; mt < 2; mt++) {
                    MMA_BF16(acc[mt][nt], ahi[mt], bh0, bh1);
                    MMA_BF16(acc[mt][nt], alo[mt], bh0, bh1);
                    MMA_BF16(acc[mt][nt], ahi[mt], bl0, bl1);
                }
            }
        }
        __syncthreads();
        if (kc + 2 < nk) issue(kc + 2);
    }

    // Epilogue: c0,c1 at (row, col..+1); c2,c3 at (row+8)
    #pragma unroll
    for (int mt = 0; mt < 2; mt++) {
        const int r0 = m0 + warp_row*32 + mt*16 + lr;
        #pragma unroll
        for (int nt = 0; nt < 8; nt++) {
            const int col = n0 + warp_col*64 + nt*8 + lc*2;
            const float2 bv = *(const float2*)(bias + col);
            float2 v0 = make_float2(acc[mt][nt][0] + bv.x, acc[mt][nt][1] + bv.y);
            float2 v1 = make_float2(acc[mt][nt][2] + bv.x, acc[mt][nt][3] + bv.y);
            *(float2*)(C + (size_t)r0 * Ndim + col)     = v0;
            *(float2*)(C + (size_t)(r0+8) * Ndim + col) = v1;
        }
    }
}

// ---------------------------------------------------------------------------
// Flash attention with shared latent (K == V). fp32 CUDA-core math.
// ---------------------------------------------------------------------------
__global__ void attn_kernel(const float* __restrict__ gq,
                            const float* __restrict__ gk,
                            float* __restrict__ gy)
{
    extern __shared__ float smf[];
    float* Qs = smf;                  // 64 x 132
    float* Ks = smf + 64*132;         // 64 x 132
    float* Ps = smf + 2*64*132;       // 64 x 68

    const int tid = threadIdx.x;
    const int tx = tid & 15, ty = tid >> 4;
    const int qt = blockIdx.x;
    const int bh = blockIdx.y;
    const int b = bh >> 4, h = bh & 15;

    const float* qbase = gq + ((size_t)b * TSEQ + qt*64) * QSTR + (size_t)h * LDIM;
    const float* kbase = gk + (size_t)b * TSEQ * LDIM;

    #pragma unroll
    for (int u = 0; u < 8; u++) {
        int lin = u*256 + tid;
        int row = lin >> 5, c4 = (lin & 31) << 2;
        *(float4*)&Qs[row*132 + c4] = *(const float4*)(qbase + (size_t)row*QSTR + c4);
    }

    float yacc[4][8];
    #pragma unroll
    for (int i = 0; i < 4; i++)
        #pragma unroll
        for (int j = 0; j < 8; j++) yacc[i][j] = 0.f;
    float m_r[4] = {-1e30f,-1e30f,-1e30f,-1e30f};
    float l_r[4] = {0.f,0.f,0.f,0.f};
    const float scale = 0.08838834764831845f;   // 1/sqrt(128)

    for (int kt = 0; kt <= qt; kt++) {
        __syncthreads();
        #pragma unroll
        for (int u = 0; u < 8; u++) {
            int lin = u*256 + tid;
            int row = lin >> 5, c4 = (lin & 31) << 2;
            *(float4*)&Ks[row*132 + c4] =
                *(const float4*)(kbase + (size_t)(kt*64 + row)*LDIM + c4);
        }
        __syncthreads();

        float sacc[4][4];
        #pragma unroll
        for (int i = 0; i < 4; i++)
            #pragma unroll
            for (int j = 0; j < 4; j++) sacc[i][j] = 0.f;

        #pragma unroll 2
        for (int kk = 0; kk < 128; kk += 4) {
            float4 qv[4], kv[4];
            #pragma unroll
            for (int i = 0; i < 4; i++)
                qv[i] = *(const float4*)&Qs[(4*ty+i)*132 + kk];
            #pragma unroll
            for (int j = 0; j < 4; j++)
                kv[j] = *(const float4*)&Ks[(tx + 16*j)*132 + kk];
            #pragma unroll
            for (int i = 0; i < 4; i++)
                #pragma unroll
                for (int j = 0; j < 4; j++)
                    sacc[i][j] += qv[i].x*kv[j].x + qv[i].y*kv[j].y
                                + qv[i].z*kv[j].z + qv[i].w*kv[j].w;
        }

        if (kt == qt) {
            #pragma unroll
            for (int i = 0; i < 4; i++)
                #pragma unroll
                for (int j = 0; j < 4; j++) {
                    if (tx + 16*j > 4*ty + i) sacc[i][j] = -1e30f;
                    else                      sacc[i][j] *= scale;
                }
        } else {
            #pragma unroll
            for (int i = 0; i < 4; i++)
                #pragma unroll
                for (int j = 0; j < 4; j++) sacc[i][j] *= scale;
        }

        #pragma unroll
        for (int i = 0; i < 4; i++) {
            float rmax = fmaxf(fmaxf(sacc[i][0], sacc[i][1]),
                               fmaxf(sacc[i][2], sacc[i][3]));
            #pragma unroll
            for (int off = 8; off > 0; off >>= 1)
                rmax = fmaxf(rmax, __shfl_xor_sync(0xffffffffu, rmax, off, 16));
            float mnew = fmaxf(m_r[i], rmax);
            float p0 = __expf(sacc[i][0] - mnew);
            float p1 = __expf(sacc[i][1] - mnew);
            float p2 = __expf(sacc[i][2] - mnew);
            float p3 = __expf(sacc[i][3] - mnew);
            float rsum = p0 + p1 + p2 + p3;
            #pragma unroll
            for (int off = 8; off > 0; off >>= 1)
                rsum += __shfl_xor_sync(0xffffffffu, rsum, off, 16);
            float corr = __expf(m_r[i] - mnew);
            l_r[i] = l_r[i]*corr + rsum;
            m_r[i] = mnew;
            Ps[(4*ty+i)*68 + tx]      = p0;
            Ps[(4*ty+i)*68 + tx + 16] = p1;
            Ps[(4*ty+i)*68 + tx + 32] = p2;
            Ps[(4*ty+i)*68 + tx + 48] = p3;
            #pragma unroll
            for (int j = 0; j < 8; j++) yacc[i][j] *= corr;
        }
        __syncwarp();

        #pragma unroll 2
        for (int s0 = 0; s0 < 64; s0 += 4) {
            float4 pv[4];
            #pragma unroll
            for (int i = 0; i < 4; i++)
                pv[i] = *(const float4*)&Ps[(4*ty+i)*68 + s0];
            #pragma unroll
            for (int u = 0; u < 4; u++) {
                float4 k0v = *(const float4*)&Ks[(s0+u)*132 + 4*tx];
                float4 k1v = *(const float4*)&Ks[(s0+u)*132 + 64 + 4*tx];
                #pragma unroll
                for (int i = 0; i < 4; i++) {
                    float p = (u==0) ? pv[i].x : (u==1) ? pv[i].y
                            : (u==2) ? pv[i].z : pv[i].w;
                    yacc[i][0] += p*k0v.x; yacc[i][1] += p*k0v.y;
                    yacc[i][2] += p*k0v.z; yacc[i][3] += p*k0v.w;
                    yacc[i][4] += p*k1v.x; yacc[i][5] += p*k1v.y;
                    yacc[i][6] += p*k1v.z; yacc[i][7] += p*k1v.w;
                }
            }
        }
    }

    #pragma unroll
    for (int i = 0; i < 4; i++) {
        float linv = 1.0f / l_r[i];
        int grow = qt*64 + 4*ty + i;
        size_t orow = ((size_t)b*TSEQ + grow)*QSTR + (size_t)h*LDIM;
        float4 v0 = make_float4(yacc[i][0]*linv, yacc[i][1]*linv,
                                yacc[i][2]*linv, yacc[i][3]*linv);
        float4 v1 = make_float4(yacc[i][4]*linv, yacc[i][5]*linv,
                                yacc[i][6]*linv, yacc[i][7]*linv);
        *(float4*)&gy[orow + 4*tx]      = v0;
        *(float4*)&gy[orow + 64 + 4*tx] = v1;
    }
}

// ---------------------------------------------------------------------------
extern "C" void kernel_launch(void* const* d_in, const int* in_sizes, int n_in,
                              void* d_out, int out_size)
{
    const float* x      = (const float*)d_in[0];
    const float* W_lat  = (const float*)d_in[1];
    const float* b_lat  = (const float*)d_in[2];
    const float* W_d    = (const float*)d_in[3];
    const float* b_d    = (const float*)d_in[4];
    const float* W_proj = (const float*)d_in[5];
    const float* b_proj = (const float*)d_in[6];
    float* out = (float*)d_out;

    float *kp, *qp, *yp;
    __nv_bfloat16 *xh, *xl, *yh, *yl;
    uint32_t *wdh, *wdl, *wph, *wpl, *wlh, *wll;
    cudaGetSymbolAddress((void**)&kp,  g_k);
    cudaGetSymbolAddress((void**)&qp,  g_q);
    cudaGetSymbolAddress((void**)&yp,  g_y);
    cudaGetSymbolAddress((void**)&xh,  g_xh);
    cudaGetSymbolAddress((void**)&xl,  g_xl);
    cudaGetSymbolAddress((void**)&yh,  g_yh);
    cudaGetSymbolAddress((void**)&yl,  g_yl);
    cudaGetSymbolAddress((void**)&wdh, g_wdh);
    cudaGetSymbolAddress((void**)&wdl, g_wdl);
    cudaGetSymbolAddress((void**)&wph, g_wph);
    cudaGetSymbolAddress((void**)&wpl, g_wpl);
    cudaGetSymbolAddress((void**)&wlh, g_wlh);
    cudaGetSymbolAddress((void**)&wll, g_wll);

    cudaFuncSetAttribute(gemm_bf16x3,
                         cudaFuncAttributeMaxDynamicSharedMemorySize, GEMM_SMEM);

    // Preprocess: split x; split+pack weights
    split_rows<<<(MROWS*CEMB/4 + 255)/256, 256>>>(x, xh, xl, MROWS*CEMB);
    split_pack<<<((CEMB/2)*QSTR + 255)/256, 256>>>(W_d,    wdh, wdl, CEMB, QSTR);
    split_pack<<<((QSTR/2)*CEMB + 255)/256, 256>>>(W_proj, wph, wpl, QSTR, CEMB);
    split_pack<<<((CEMB/2)*LDIM + 255)/256, 256>>>(W_lat,  wlh, wll, CEMB, LDIM);

    // 1) k = x @ W_lat + b_lat     [4096,128]
    gemm_bf16x3<<<dim3(1, MROWS/128), 256, GEMM_SMEM>>>(xh, xl, wlh, wll,
                                                        b_lat, kp, LDIM, CEMB);
    // 2) q = x @ W_d + b_d         [4096,2048]
    gemm_bf16x3<<<dim3(QSTR/128, MROWS/128), 256, GEMM_SMEM>>>(xh, xl, wdh, wdl,
                                                        b_d, qp, QSTR, CEMB);
    // 3) flash attention (K == V)
    const int attn_smem = (2*64*132 + 64*68) * (int)sizeof(float);  // 84,992 B
    cudaFuncSetAttribute(attn_kernel,
                         cudaFuncAttributeMaxDynamicSharedMemorySize, attn_smem);
    attn_kernel<<<dim3(TSEQ/64, BATCH*NHEAD), 256, attn_smem>>>(qp, kp, yp);

    // 4) split y, then out = y @ W_proj + b_proj
    split_rows<<<(MROWS*QSTR/4 + 255)/256, 256>>>(yp, yh, yl, MROWS*QSTR);
    gemm_bf16x3<<<dim3(CEMB/128, MROWS/128), 256, GEMM_SMEM>>>(yh, yl, wph, wpl,
                                                        b_proj, out, CEMB, CEMB);
}

// round 6
// speedup vs baseline: 2.6693x; 2.5810x over previous
#include <cuda_runtime.h>
#include <cuda_bf16.h>
#include <cstdint>

#define BATCH 2
#define TSEQ 2048
#define CEMB 2048
#define NHEAD 16
#define LDIM 128
#define MROWS (BATCH*TSEQ)
#define QSTR (NHEAD*LDIM)   // 2048

// ---------------------------------------------------------------------------
// Scratch (__device__ globals: allocation-free rule)
// ---------------------------------------------------------------------------
__device__ __nv_bfloat16 g_xh[MROWS*CEMB], g_xl[MROWS*CEMB];   // x split
__device__ __nv_bfloat16 g_qh[MROWS*QSTR], g_ql[MROWS*QSTR];   // q split
__device__ __nv_bfloat16 g_kh[MROWS*LDIM], g_kl[MROWS*LDIM];   // k latent split
__device__ __nv_bfloat16 g_yh[MROWS*QSTR], g_yl[MROWS*QSTR];   // y split
__device__ uint32_t g_wdh[QSTR*(CEMB/2)], g_wdl[QSTR*(CEMB/2)];  // W_d  [N][K/2]
__device__ uint32_t g_wph[CEMB*(QSTR/2)], g_wpl[CEMB*(QSTR/2)];  // W_proj
__device__ uint32_t g_wlh[LDIM*(CEMB/2)], g_wll[LDIM*(CEMB/2)];  // W_lat

// ---------------------------------------------------------------------------
// Helpers
// ---------------------------------------------------------------------------
__device__ __forceinline__ uint32_t smem_u32(const void* p){
    uint32_t a;
    asm("{ .reg .u64 t; cvta.to.shared.u64 t, %1; cvt.u32.u64 %0, t; }"
        : "=r"(a) : "l"(p));
    return a;
}
__device__ __forceinline__ float bfround(float x){
    return __bfloat162float(__float2bfloat16(x));
}
__device__ __forceinline__ uint32_t pack2(float lo, float hi){
    uint32_t r;
    asm("cvt.rn.bf16x2.f32 %0, %1, %2;" : "=r"(r) : "f"(hi), "f"(lo));
    return r;
}

#define CP16(dst_u32, src_ptr) \
    asm volatile("cp.async.cg.shared.global [%0], [%1], 16;" \
                 :: "r"(dst_u32), "l"(src_ptr) : "memory")
#define CP_COMMIT() asm volatile("cp.async.commit_group;" ::: "memory")
#define CP_WAIT(n)  asm volatile("cp.async.wait_group %0;" :: "n"(n) : "memory")

#define LDSM4(R, ADDR)                                                        \
    asm volatile("ldmatrix.sync.aligned.m8n8.x4.shared.b16 {%0,%1,%2,%3}, [%4];" \
        : "=r"((R)[0]), "=r"((R)[1]), "=r"((R)[2]), "=r"((R)[3]) : "r"(ADDR))
#define LDSM4T(R, ADDR)                                                       \
    asm volatile("ldmatrix.sync.aligned.m8n8.x4.trans.shared.b16 {%0,%1,%2,%3}, [%4];" \
        : "=r"((R)[0]), "=r"((R)[1]), "=r"((R)[2]), "=r"((R)[3]) : "r"(ADDR))

#define MMA_BF16(acc, a, b0, b1)                                              \
    asm volatile(                                                             \
        "mma.sync.aligned.m16n8k16.row.col.f32.bf16.bf16.f32 "                \
        "{%0,%1,%2,%3}, {%4,%5,%6,%7}, {%8,%9}, {%0,%1,%2,%3};"               \
        : "+f"((acc)[0]), "+f"((acc)[1]), "+f"((acc)[2]), "+f"((acc)[3])      \
        : "r"((a)[0]), "r"((a)[1]), "r"((a)[2]), "r"((a)[3]),                 \
          "r"(b0), "r"(b1))

// ---------------------------------------------------------------------------
// Split fp32 -> (hi, lo) bf16 (A-side operands)
// ---------------------------------------------------------------------------
__global__ void split_rows(const float* __restrict__ src,
                           __nv_bfloat16* __restrict__ hi,
                           __nv_bfloat16* __restrict__ lo, int n)
{
    int i = (blockIdx.x * 256 + threadIdx.x) * 4;
    if (i >= n) return;
    float4 v = *(const float4*)(src + i);
    *(uint32_t*)(hi + i)     = pack2(bfround(v.x), bfround(v.y));
    *(uint32_t*)(hi + i + 2) = pack2(bfround(v.z), bfround(v.w));
    *(uint32_t*)(lo + i)     = pack2(v.x - bfround(v.x), v.y - bfround(v.y));
    *(uint32_t*)(lo + i + 2) = pack2(v.z - bfround(v.z), v.w - bfround(v.w));
}

// ---------------------------------------------------------------------------
// Split + transpose-pack:  W[K][N] -> hi/lo u32 [N][K/2] (k-pairs packed)
// ---------------------------------------------------------------------------
__global__ void split_pack_t(const float* __restrict__ W,
                             uint32_t* __restrict__ hp,
                             uint32_t* __restrict__ lp, int K, int N)
{
    __shared__ float t[32][33];
    const int k0 = blockIdx.x * 32, n0 = blockIdx.y * 32;
    const int tx = threadIdx.x, ty = threadIdx.y;
    for (int i = ty; i < 32; i += 8)
        t[i][tx] = W[(size_t)(k0 + i) * N + n0 + tx];
    __syncthreads();
    if (tx < 16) {
        for (int i = ty; i < 32; i += 8) {
            float v0 = t[2*tx][i], v1 = t[2*tx+1][i];
            size_t o = (size_t)(n0 + i) * (K >> 1) + (k0 >> 1) + tx;
            hp[o] = pack2(bfround(v0), bfround(v1));
            lp[o] = pack2(v0 - bfround(v0), v1 - bfround(v1));
        }
    }
}

// ---------------------------------------------------------------------------
// bf16x3 GEMM with ldmatrix:  C[M,N] = A[M,K] @ B + bias
// A: hi/lo bf16 [M][K]. B: hi/lo u32 [N][K/2].
// CTA 128x128, BK=32, 256 thr (8 warps 4x2), warp 32x64. cp.async dbl-buf.
// OUT_SPLIT=0: fp32 C.  OUT_SPLIT=1: bf16 hi/lo pair outputs.
// ---------------------------------------------------------------------------
#define SROWB 80                         // 16 u32 data + 4 pad (bank-cycling)
#define REGB  (128*SROWB)                // 10240 per operand region
#define OFF_AH 0
#define OFF_AL REGB
#define OFF_BH (2*REGB)
#define OFF_BL (3*REGB)
#define STAGE  (4*REGB)                  // 40960
#define GEMM_SMEM (2*STAGE)              // 81920

template<int OUT_SPLIT>
__global__ void __launch_bounds__(256, 2)
gemm_bf16x3(const __nv_bfloat16* __restrict__ Ah,
            const __nv_bfloat16* __restrict__ Al,
            const uint32_t* __restrict__ Bh,
            const uint32_t* __restrict__ Bl,
            const float* __restrict__ bias,
            float* __restrict__ C,
            __nv_bfloat16* __restrict__ Ch,
            __nv_bfloat16* __restrict__ Cl,
            int Ndim, int Kdim)
{
    extern __shared__ char sm[];
    const uint32_t smb = smem_u32(sm);
    const int tid = threadIdx.x;
    const int lane = tid & 31, wid = tid >> 5;
    const int warp_row = wid & 3, warp_col = wid >> 2;
    const int m0 = blockIdx.y << 7, n0 = blockIdx.x << 7;
    const int lr = lane >> 2, lc = lane & 3;
    const int KH = Kdim >> 1;

    float acc[2][8][4];
    #pragma unroll
    for (int mt = 0; mt < 2; mt++)
        #pragma unroll
        for (int nt = 0; nt < 8; nt++)
            #pragma unroll
            for (int i = 0; i < 4; i++) acc[mt][nt][i] = 0.f;

    const int crow = tid >> 2, cch = tid & 3;   // 64 rows x 4 chunks per pass
    const int nk = Kdim >> 5;

    auto issue = [&](int kc) {
        const uint32_t base = smb + (kc & 1) * STAGE;
        const int k0 = kc << 5, kp0 = kc << 4;
        #pragma unroll
        for (int p = 0; p < 2; p++) {
            int row = p * 64 + crow;
            uint32_t d = base + row * SROWB + cch * 16;
            CP16(d + OFF_AH, Ah + (size_t)(m0 + row) * Kdim + k0 + cch * 8);
            CP16(d + OFF_AL, Al + (size_t)(m0 + row) * Kdim + k0 + cch * 8);
            CP16(d + OFF_BH, Bh + (size_t)(n0 + row) * KH + kp0 + cch * 4);
            CP16(d + OFF_BL, Bl + (size_t)(n0 + row) * KH + kp0 + cch * 4);
        }
        CP_COMMIT();
    };

    issue(0);
    if (nk > 1) issue(1);

    // ldmatrix lane-address components
    const int a_row = lane & 15, a_koff = lane & 16;
    const int b_row = (lane & 7) + ((lane & 16) ? 8 : 0);
    const int b_koff = (lane & 8) ? 16 : 0;

    for (int kc = 0; kc < nk; kc++) {
        if (kc + 1 < nk) CP_WAIT(1); else CP_WAIT(0);
        __syncthreads();
        const uint32_t base = smb + (kc & 1) * STAGE;

        #pragma unroll
        for (int ks = 0; ks < 2; ks++) {
            uint32_t ah[2][4], al[2][4];
            #pragma unroll
            for (int mt = 0; mt < 2; mt++) {
                uint32_t aa = base + OFF_AH
                            + (warp_row*32 + mt*16 + a_row) * SROWB
                            + ks*32 + a_koff;
                LDSM4(ah[mt], aa);
                LDSM4(al[mt], aa + (OFF_AL - OFF_AH));
            }
            #pragma unroll
            for (int np = 0; np < 4; np++) {
                uint32_t ba = base + OFF_BH
                            + (warp_col*64 + np*16 + b_row) * SROWB
                            + ks*32 + b_koff;
                uint32_t bh4[4], bl4[4];
                LDSM4(bh4, ba);
                LDSM4(bl4, ba + (OFF_BL - OFF_BH));
                #pragma unroll
                for (int sub = 0; sub < 2; sub++) {
                    #pragma unroll
                    for (int mt = 0; mt < 2; mt++) {
                        MMA_BF16(acc[mt][2*np+sub], ah[mt], bh4[2*sub], bh4[2*sub+1]);
                        MMA_BF16(acc[mt][2*np+sub], al[mt], bh4[2*sub], bh4[2*sub+1]);
                        MMA_BF16(acc[mt][2*np+sub], ah[mt], bl4[2*sub], bl4[2*sub+1]);
                    }
                }
            }
        }
        __syncthreads();
        if (kc + 2 < nk) issue(kc + 2);
    }

    #pragma unroll
    for (int mt = 0; mt < 2; mt++) {
        const int r0 = m0 + warp_row*32 + mt*16 + lr;
        #pragma unroll
        for (int nt = 0; nt < 8; nt++) {
            const int col = n0 + warp_col*64 + nt*8 + lc*2;
            const float2 bv = *(const float2*)(bias + col);
            float v0 = acc[mt][nt][0] + bv.x, v1 = acc[mt][nt][1] + bv.y;
            float v2 = acc[mt][nt][2] + bv.x, v3 = acc[mt][nt][3] + bv.y;
            if (OUT_SPLIT) {
                *(uint32_t*)(Ch + (size_t)r0 * Ndim + col) = pack2(v0, v1);
                *(uint32_t*)(Cl + (size_t)r0 * Ndim + col) =
                    pack2(v0 - bfround(v0), v1 - bfround(v1));
                *(uint32_t*)(Ch + (size_t)(r0+8) * Ndim + col) = pack2(v2, v3);
                *(uint32_t*)(Cl + (size_t)(r0+8) * Ndim + col) =
                    pack2(v2 - bfround(v2), v3 - bfround(v3));
            } else {
                *(float2*)(C + (size_t)r0 * Ndim + col)     = make_float2(v0, v1);
                *(float2*)(C + (size_t)(r0+8) * Ndim + col) = make_float2(v2, v3);
            }
        }
    }
}

// ---------------------------------------------------------------------------
// Tensor-core flash attention, shared latent (K == V), bf16x3 accuracy.
// CTA: 256 thr (8 warps), q-tile 128 rows (warp w: rows w*16..+15).
// K tile: 64 s-rows x 128, hi+lo, cp.async double-buffered.
// S = QK^T via mma (Q frags persistent); P packed from regs (FA2 layout);
// Y += P K via mma with ldmatrix.trans on the same K tile.
// ---------------------------------------------------------------------------
#define KROWB 272                        // 128 bf16 = 256B data + 16B pad
#define STG_L (64*KROWB)                 // lo half offset within a stage
#define STAGE_A (2*64*KROWB)             // 34816 per stage (hi+lo)
#define Q_OFF (2*STAGE_A)                // 69632
#define ATTN_SMEM (2*STAGE_A + 128*KROWB)  // 104448

__global__ void __launch_bounds__(256, 1)
attn_kernel(const __nv_bfloat16* __restrict__ qh,
            const __nv_bfloat16* __restrict__ ql,
            const __nv_bfloat16* __restrict__ kh,
            const __nv_bfloat16* __restrict__ kl,
            __nv_bfloat16* __restrict__ yh,
            __nv_bfloat16* __restrict__ yl)
{
    extern __shared__ char sm[];
    const uint32_t smb = smem_u32(sm);
    const int tid = threadIdx.x;
    const int lane = tid & 31, w = tid >> 5;
    const int lr = lane >> 2, lc = lane & 3;
    const int qt = blockIdx.x, bhid = blockIdx.y;
    const int b = bhid >> 4, h = bhid & 15;

    const char* qbh = (const char*)(qh + ((size_t)b*TSEQ + qt*128)*QSTR + h*LDIM);
    const char* qbl = (const char*)(ql + ((size_t)b*TSEQ + qt*128)*QSTR + h*LDIM);
    const char* kbh = (const char*)(kh + (size_t)b*TSEQ*LDIM);
    const char* kbl = (const char*)(kl + (size_t)b*TSEQ*LDIM);

    // ---- Prologue: Q fragments (hi then lo through the Q staging region)
    uint32_t qfh[8][4], qfl[8][4];
    {
        const int qrow = tid >> 4, qch = tid & 15;
        #pragma unroll
        for (int p = 0; p < 8; p++) {
            int row = p*16 + qrow;
            CP16(smb + Q_OFF + row*KROWB + qch*16, qbh + (size_t)row*QSTR*2 + qch*16);
        }
        CP_COMMIT(); CP_WAIT(0); __syncthreads();
        #pragma unroll
        for (int ks = 0; ks < 8; ks++) {
            uint32_t a = smb + Q_OFF + (w*16 + (lane & 15))*KROWB + ks*32 + (lane & 16);
            LDSM4(qfh[ks], a);
        }
        __syncthreads();
        #pragma unroll
        for (int p = 0; p < 8; p++) {
            int row = p*16 + qrow;
            CP16(smb + Q_OFF + row*KROWB + qch*16, qbl + (size_t)row*QSTR*2 + qch*16);
        }
        CP_COMMIT(); CP_WAIT(0); __syncthreads();
        #pragma unroll
        for (int ks = 0; ks < 8; ks++) {
            uint32_t a = smb + Q_OFF + (w*16 + (lane & 15))*KROWB + ks*32 + (lane & 16);
            LDSM4(qfl[ks], a);
        }
        __syncthreads();
    }

    float yacc[16][4];
    #pragma unroll
    for (int nt = 0; nt < 16; nt++)
        #pragma unroll
        for (int i = 0; i < 4; i++) yacc[nt][i] = 0.f;
    float m0 = -1e30f, m1 = -1e30f, l0 = 0.f, l1 = 0.f;

    const int nkt = 2*qt + 2;
    const int krow = tid >> 4, kch = tid & 15;

    auto issueK = [&](int kt) {
        const uint32_t base = smb + (kt & 1) * STAGE_A;
        #pragma unroll
        for (int p = 0; p < 4; p++) {
            int row = p*16 + krow;
            uint32_t d = base + row*KROWB + kch*16;
            CP16(d,         kbh + (size_t)(kt*64 + row)*256 + kch*16);
            CP16(d + STG_L, kbl + (size_t)(kt*64 + row)*256 + kch*16);
        }
        CP_COMMIT();
    };

    issueK(0);
    if (nkt > 1) issueK(1);

    const float scale = 0.08838834764831845f;   // 1/sqrt(128)
    const int t0g = qt*128 + w*16 + lr, t1g = t0g + 8;

    for (int kt = 0; kt < nkt; kt++) {
        if (kt + 1 < nkt) CP_WAIT(1); else CP_WAIT(0);
        __syncthreads();
        const uint32_t base = smb + (kt & 1) * STAGE_A;

        // ---- S = Q K^T  (m16 x s64 x l128 per warp), bf16x3
        float sacc[8][4];
        #pragma unroll
        for (int nt = 0; nt < 8; nt++)
            #pragma unroll
            for (int i = 0; i < 4; i++) sacc[nt][i] = 0.f;

        const int sb_row = (lane & 7) + ((lane & 16) ? 8 : 0);
        const int sb_koff = (lane & 8) ? 16 : 0;
        #pragma unroll
        for (int ks = 0; ks < 8; ks++) {
            #pragma unroll
            for (int np = 0; np < 4; np++) {
                uint32_t ba = base + (np*16 + sb_row)*KROWB + ks*32 + sb_koff;
                uint32_t bh4[4], bl4[4];
                LDSM4(bh4, ba);
                LDSM4(bl4, ba + STG_L);
                #pragma unroll
                for (int sub = 0; sub < 2; sub++) {
                    MMA_BF16(sacc[2*np+sub], qfh[ks], bh4[2*sub], bh4[2*sub+1]);
                    MMA_BF16(sacc[2*np+sub], qfl[ks], bh4[2*sub], bh4[2*sub+1]);
                    MMA_BF16(sacc[2*np+sub], qfh[ks], bl4[2*sub], bl4[2*sub+1]);
                }
            }
        }

        // ---- scale + causal mask (only the two diagonal-band tiles)
        #pragma unroll
        for (int nt = 0; nt < 8; nt++)
            #pragma unroll
            for (int i = 0; i < 4; i++) sacc[nt][i] *= scale;
        if (kt >= 2*qt) {
            #pragma unroll
            for (int nt = 0; nt < 8; nt++) {
                int s0 = kt*64 + nt*8 + 2*lc;
                if (s0     > t0g) sacc[nt][0] = -1e30f;
                if (s0 + 1 > t0g) sacc[nt][1] = -1e30f;
                if (s0     > t1g) sacc[nt][2] = -1e30f;
                if (s0 + 1 > t1g) sacc[nt][3] = -1e30f;
            }
        }

        // ---- online softmax (rows t0g, t1g; quad-wide shuffles)
        float mx0 = -1e30f, mx1 = -1e30f;
        #pragma unroll
        for (int nt = 0; nt < 8; nt++) {
            mx0 = fmaxf(mx0, fmaxf(sacc[nt][0], sacc[nt][1]));
            mx1 = fmaxf(mx1, fmaxf(sacc[nt][2], sacc[nt][3]));
        }
        mx0 = fmaxf(mx0, __shfl_xor_sync(0xffffffffu, mx0, 1));
        mx0 = fmaxf(mx0, __shfl_xor_sync(0xffffffffu, mx0, 2));
        mx1 = fmaxf(mx1, __shfl_xor_sync(0xffffffffu, mx1, 1));
        mx1 = fmaxf(mx1, __shfl_xor_sync(0xffffffffu, mx1, 2));
        float m0n = fmaxf(m0, mx0), m1n = fmaxf(m1, mx1);
        float c0 = __expf(m0 - m0n), c1 = __expf(m1 - m1n);
        float s0sum = 0.f, s1sum = 0.f;
        #pragma unroll
        for (int nt = 0; nt < 8; nt++) {
            float p0 = __expf(sacc[nt][0] - m0n);
            float p1 = __expf(sacc[nt][1] - m0n);
            float p2 = __expf(sacc[nt][2] - m1n);
            float p3 = __expf(sacc[nt][3] - m1n);
            s0sum += p0 + p1; s1sum += p2 + p3;
            sacc[nt][0] = p0; sacc[nt][1] = p1; sacc[nt][2] = p2; sacc[nt][3] = p3;
        }
        s0sum += __shfl_xor_sync(0xffffffffu, s0sum, 1);
        s0sum += __shfl_xor_sync(0xffffffffu, s0sum, 2);
        s1sum += __shfl_xor_sync(0xffffffffu, s1sum, 1);
        s1sum += __shfl_xor_sync(0xffffffffu, s1sum, 2);
        l0 = l0*c0 + s0sum; l1 = l1*c1 + s1sum;
        m0 = m0n; m1 = m1n;
        #pragma unroll
        for (int nt = 0; nt < 16; nt++) {
            yacc[nt][0] *= c0; yacc[nt][1] *= c0;
            yacc[nt][2] *= c1; yacc[nt][3] *= c1;
        }

        // ---- Y += P K  (m16 x l128 x s64 per warp), bf16x3, K via ldmatrix.trans
        #pragma unroll
        for (int ks2 = 0; ks2 < 4; ks2++) {
            // P A-frags from accumulators (FA2 layout): hi + lo splits
            uint32_t pah[4], pal[4];
            {
                float p0 = sacc[2*ks2][0], p1 = sacc[2*ks2][1];
                float p2 = sacc[2*ks2][2], p3 = sacc[2*ks2][3];
                float q0 = sacc[2*ks2+1][0], q1 = sacc[2*ks2+1][1];
                float q2 = sacc[2*ks2+1][2], q3 = sacc[2*ks2+1][3];
                pah[0] = pack2(p0, p1); pah[1] = pack2(p2, p3);
                pah[2] = pack2(q0, q1); pah[3] = pack2(q2, q3);
                pal[0] = pack2(p0 - bfround(p0), p1 - bfround(p1));
                pal[1] = pack2(p2 - bfround(p2), p3 - bfround(p3));
                pal[2] = pack2(q0 - bfround(q0), q1 - bfround(q1));
                pal[3] = pack2(q2 - bfround(q2), q3 - bfround(q3));
            }
            #pragma unroll
            for (int np = 0; np < 8; np++) {
                uint32_t va = base + (ks2*16 + (lane & 15))*KROWB
                            + np*32 + (lane & 16);
                uint32_t vh4[4], vl4[4];
                LDSM4T(vh4, va);
                LDSM4T(vl4, va + STG_L);
                #pragma unroll
                for (int sub = 0; sub < 2; sub++) {
                    MMA_BF16(yacc[2*np+sub], pah, vh4[2*sub], vh4[2*sub+1]);
                    MMA_BF16(yacc[2*np+sub], pal, vh4[2*sub], vh4[2*sub+1]);
                    MMA_BF16(yacc[2*np+sub], pah, vl4[2*sub], vl4[2*sub+1]);
                }
            }
        }
        __syncthreads();
        if (kt + 2 < nkt) issueK(kt + 2);
    }

    // ---- Epilogue: normalize, split to bf16 hi/lo, write y
    const float li0 = 1.0f / l0, li1 = 1.0f / l1;
    #pragma unroll
    for (int nt = 0; nt < 16; nt++) {
        float v0 = yacc[nt][0]*li0, v1 = yacc[nt][1]*li0;
        float v2 = yacc[nt][2]*li1, v3 = yacc[nt][3]*li1;
        size_t o0 = ((size_t)b*TSEQ + t0g)*QSTR + h*LDIM + nt*8 + 2*lc;
        size_t o1 = o0 + (size_t)8*QSTR;
        *(uint32_t*)(yh + o0) = pack2(v0, v1);
        *(uint32_t*)(yl + o0) = pack2(v0 - bfround(v0), v1 - bfround(v1));
        *(uint32_t*)(yh + o1) = pack2(v2, v3);
        *(uint32_t*)(yl + o1) = pack2(v2 - bfround(v2), v3 - bfround(v3));
    }
}

// ---------------------------------------------------------------------------
extern "C" void kernel_launch(void* const* d_in, const int* in_sizes, int n_in,
                              void* d_out, int out_size)
{
    const float* x      = (const float*)d_in[0];
    const float* W_lat  = (const float*)d_in[1];
    const float* b_lat  = (const float*)d_in[2];
    const float* W_d    = (const float*)d_in[3];
    const float* b_d    = (const float*)d_in[4];
    const float* W_proj = (const float*)d_in[5];
    const float* b_proj = (const float*)d_in[6];
    float* out = (float*)d_out;

    __nv_bfloat16 *xh, *xl, *qhp, *qlp, *khp, *klp, *yhp, *ylp;
    uint32_t *wdh, *wdl, *wph, *wpl, *wlh, *wll;
    cudaGetSymbolAddress((void**)&xh,  g_xh);
    cudaGetSymbolAddress((void**)&xl,  g_xl);
    cudaGetSymbolAddress((void**)&qhp, g_qh);
    cudaGetSymbolAddress((void**)&qlp, g_ql);
    cudaGetSymbolAddress((void**)&khp, g_kh);
    cudaGetSymbolAddress((void**)&klp, g_kl);
    cudaGetSymbolAddress((void**)&yhp, g_yh);
    cudaGetSymbolAddress((void**)&ylp, g_yl);
    cudaGetSymbolAddress((void**)&wdh, g_wdh);
    cudaGetSymbolAddress((void**)&wdl, g_wdl);
    cudaGetSymbolAddress((void**)&wph, g_wph);
    cudaGetSymbolAddress((void**)&wpl, g_wpl);
    cudaGetSymbolAddress((void**)&wlh, g_wlh);
    cudaGetSymbolAddress((void**)&wll, g_wll);

    cudaFuncSetAttribute(gemm_bf16x3<0>,
                         cudaFuncAttributeMaxDynamicSharedMemorySize, GEMM_SMEM);
    cudaFuncSetAttribute(gemm_bf16x3<1>,
                         cudaFuncAttributeMaxDynamicSharedMemorySize, GEMM_SMEM);
    cudaFuncSetAttribute(attn_kernel,
                         cudaFuncAttributeMaxDynamicSharedMemorySize, ATTN_SMEM);

    // Preprocess
    split_rows<<<(MROWS*CEMB/4 + 255)/256, 256>>>(x, xh, xl, MROWS*CEMB);
    dim3 tb(32, 8);
    split_pack_t<<<dim3(CEMB/32, QSTR/32), tb>>>(W_d,    wdh, wdl, CEMB, QSTR);
    split_pack_t<<<dim3(QSTR/32, CEMB/32), tb>>>(W_proj, wph, wpl, QSTR, CEMB);
    split_pack_t<<<dim3(CEMB/32, LDIM/32), tb>>>(W_lat,  wlh, wll, CEMB, LDIM);

    // 1) k latent (split output)
    gemm_bf16x3<1><<<dim3(1, MROWS/128), 256, GEMM_SMEM>>>(
        xh, xl, wlh, wll, b_lat, nullptr, khp, klp, LDIM, CEMB);
    // 2) q (split output)
    gemm_bf16x3<1><<<dim3(QSTR/128, MROWS/128), 256, GEMM_SMEM>>>(
        xh, xl, wdh, wdl, b_d, nullptr, qhp, qlp, QSTR, CEMB);
    // 3) tensor-core flash attention (K == V), writes split y
    attn_kernel<<<dim3(TSEQ/128, BATCH*NHEAD), 256, ATTN_SMEM>>>(
        qhp, qlp, khp, klp, yhp, ylp);
    // 4) out = y @ W_proj + b_proj (fp32 output)
    gemm_bf16x3<0><<<dim3(CEMB/128, MROWS/128), 256, GEMM_SMEM>>>(
        yhp, ylp, wph, wpl, b_proj, out, nullptr, nullptr, CEMB, CEMB);
}